// round 4
// baseline (speedup 1.0000x reference)
#include <cuda_runtime.h>

#define S_ 512
#define L_ 256
#define H_ 768
#define P_ 8
#define K_ 8
#define H4_ (H_/4)          // 192
#define SPAN_ 72            // 64 max entries + 8 round-up slack
#define THREADS_ 576        // 3 role-groups x 192 lanes

__global__ __launch_bounds__(THREADS_, 3)
void srl_pool_kernel(const float* __restrict__ emb,
                     const int* __restrict__ idxV,  const int* __restrict__ mV,
                     const int* __restrict__ idxA0, const int* __restrict__ mA0,
                     const int* __restrict__ idxA1, const int* __restrict__ mA1,
                     const int* __restrict__ pred,
                     float* __restrict__ out)
{
    const int s   = blockIdx.x;
    const int tid = threadIdx.x;

    __shared__ int   s_idx[3][SPAN_];
    __shared__ float s_w[3][SPAN_];
    __shared__ int   s_n[3];

    // Pre-zero lists: 3*72 = 216 slots, covered by first 216 threads.
    if (tid < 3 * SPAN_) {
        int r = tid / SPAN_, j = tid % SPAN_;
        s_idx[r][j] = 0;
        s_w[r][j]   = 0.0f;
    }
    if (tid < 3) s_n[tid] = 0;
    __syncthreads();

    // Phase 1: 24 threads, one per (role, p). Fold all gating + divisions
    // into a single per-entry weight; compact non-zero entries.
    if (tid < 3 * P_) {
        const int role = tid >> 3;
        const int p    = tid & 7;
        const int* __restrict__ idx =
            (role == 0) ? idxV : (role == 1) ? idxA0 : idxA1;
        const int* __restrict__ msk =
            (role == 0) ? mV : (role == 1) ? mA0 : mA1;

        const int base = (s * P_ + p) * K_;
        int li[K_], lv[K_];
        int cnt = 0;
        #pragma unroll
        for (int k = 0; k < K_; k++) {
            int ix = idx[base + k];
            int v  = (msk[base + k] != 0) & (ix < L_) & (ix >= 0);
            li[k]  = min(max(ix, 0), L_ - 1);
            lv[k]  = v;
            cnt   += v;
        }

        int npred = 0;
        #pragma unroll
        for (int q = 0; q < P_; q++) npred += (pred[s * P_ + q] != 0);

        float w = 0.0f;
        if ((pred[s * P_ + p] != 0) && cnt > 0 && npred > 0)
            w = 1.0f / ((float)cnt * (float)npred);

        if (w != 0.0f) {
            int pos = atomicAdd(&s_n[role], cnt);
            #pragma unroll
            for (int k = 0; k < K_; k++) {
                if (lv[k]) {
                    s_idx[role][pos] = li[k];
                    s_w[role][pos]   = w;
                    pos++;
                }
            }
        }
    }
    __syncthreads();

    // Phase 2: each 192-thread role-group runs its own weighted row-sum.
    const int role = tid / H4_;      // 0..2
    const int col  = tid % H4_;      // 0..191 -> one float4 slice of H

    const float4* __restrict__ emb4 =
        reinterpret_cast<const float4*>(emb) + (size_t)s * L_ * H4_;

    float4 acc = make_float4(0.f, 0.f, 0.f, 0.f);

    const int n = (s_n[role] + 7) & ~7;   // pad to MLP=8 batches (padded: w=0, idx=0)
    const int*   __restrict__ lidx = s_idx[role];
    const float* __restrict__ lw   = s_w[role];

    for (int j = 0; j < n; j += 8) {
        int   i0 = lidx[j+0], i1 = lidx[j+1], i2 = lidx[j+2], i3 = lidx[j+3];
        int   i4 = lidx[j+4], i5 = lidx[j+5], i6 = lidx[j+6], i7 = lidx[j+7];
        float4 v0 = emb4[i0 * H4_ + col];
        float4 v1 = emb4[i1 * H4_ + col];
        float4 v2 = emb4[i2 * H4_ + col];
        float4 v3 = emb4[i3 * H4_ + col];
        float4 v4 = emb4[i4 * H4_ + col];
        float4 v5 = emb4[i5 * H4_ + col];
        float4 v6 = emb4[i6 * H4_ + col];
        float4 v7 = emb4[i7 * H4_ + col];
        float w0 = lw[j+0], w1 = lw[j+1], w2 = lw[j+2], w3 = lw[j+3];
        float w4 = lw[j+4], w5 = lw[j+5], w6 = lw[j+6], w7 = lw[j+7];
        acc.x += w0*v0.x; acc.y += w0*v0.y; acc.z += w0*v0.z; acc.w += w0*v0.w;
        acc.x += w1*v1.x; acc.y += w1*v1.y; acc.z += w1*v1.z; acc.w += w1*v1.w;
        acc.x += w2*v2.x; acc.y += w2*v2.y; acc.z += w2*v2.z; acc.w += w2*v2.w;
        acc.x += w3*v3.x; acc.y += w3*v3.y; acc.z += w3*v3.z; acc.w += w3*v3.w;
        acc.x += w4*v4.x; acc.y += w4*v4.y; acc.z += w4*v4.z; acc.w += w4*v4.w;
        acc.x += w5*v5.x; acc.y += w5*v5.y; acc.z += w5*v5.z; acc.w += w5*v5.w;
        acc.x += w6*v6.x; acc.y += w6*v6.y; acc.z += w6*v6.z; acc.w += w6*v6.w;
        acc.x += w7*v7.x; acc.y += w7*v7.y; acc.z += w7*v7.z; acc.w += w7*v7.w;
    }

    // Output: (e_V, e_A0, e_A1) role-major, each (S, H) f32.
    float4* __restrict__ out4 = reinterpret_cast<float4*>(out);
    out4[((size_t)role * S_ + s) * H4_ + col] = acc;
}

extern "C" void kernel_launch(void* const* d_in, const int* in_sizes, int n_in,
                              void* d_out, int out_size)
{
    const float* emb   = (const float*)d_in[0];
    const int*   idxV  = (const int*)d_in[1];
    const int*   mV    = (const int*)d_in[2];
    const int*   idxA0 = (const int*)d_in[3];
    const int*   mA0   = (const int*)d_in[4];
    const int*   idxA1 = (const int*)d_in[5];
    const int*   mA1   = (const int*)d_in[6];
    const int*   pred  = (const int*)d_in[7];
    float* out = (float*)d_out;

    srl_pool_kernel<<<S_, THREADS_>>>(emb, idxV, mV, idxA0, mA0, idxA1, mA1, pred, out);
}

// round 5
// speedup vs baseline: 1.1575x; 1.1575x over previous
#include <cuda_runtime.h>

#define S_ 512
#define L_ 256
#define H_ 768
#define P_ 8
#define K_ 8
#define H4_ (H_/4)          // 192 float4 per full row
#define HH4_ (H4_/2)        // 96 float4 per half row
#define SPAN_ 68            // 64 max entries + 4 round-up slack
#define THREADS_ 96

__global__ __launch_bounds__(THREADS_, 1)
void srl_pool_kernel(const float* __restrict__ emb,
                     const int* __restrict__ idxV,  const int* __restrict__ mV,
                     const int* __restrict__ idxA0, const int* __restrict__ mA0,
                     const int* __restrict__ idxA1, const int* __restrict__ mA1,
                     const int* __restrict__ pred,
                     float* __restrict__ out)
{
    const int s     = blockIdx.x;
    const int hhalf = blockIdx.y;          // 0 or 1: which 384-float half of H
    const int tid   = threadIdx.x;         // 0..95 -> one float4 column of the half

    __shared__ int   s_idx[3][SPAN_];
    __shared__ float s_w[3][SPAN_];
    __shared__ int   s_n[3];

    // Pre-zero lists: 3*68 = 204 slots (padded slots: idx=0, w=0 -> harmless).
    #pragma unroll
    for (int j = tid; j < 3 * SPAN_; j += THREADS_) {
        s_idx[j / SPAN_][j % SPAN_] = 0;
        s_w[j / SPAN_][j % SPAN_]   = 0.0f;
    }
    if (tid < 3) s_n[tid] = 0;
    __syncthreads();

    // Phase 1: 24 threads, one per (role, p). Vectorized int4 loads.
    if (tid < 3 * P_) {
        const int role = tid >> 3;
        const int p    = tid & 7;
        const int* __restrict__ idx =
            (role == 0) ? idxV : (role == 1) ? idxA0 : idxA1;
        const int* __restrict__ msk =
            (role == 0) ? mV : (role == 1) ? mA0 : mA1;

        const int base = (s * P_ + p) * K_;   // 32B-aligned (multiple of 8 ints)
        int4 iv0 = *reinterpret_cast<const int4*>(idx + base);
        int4 iv1 = *reinterpret_cast<const int4*>(idx + base + 4);
        int4 mv0 = *reinterpret_cast<const int4*>(msk + base);
        int4 mv1 = *reinterpret_cast<const int4*>(msk + base + 4);
        int4 pv0 = *reinterpret_cast<const int4*>(pred + s * P_);
        int4 pv1 = *reinterpret_cast<const int4*>(pred + s * P_ + 4);

        int li[K_] = { iv0.x, iv0.y, iv0.z, iv0.w, iv1.x, iv1.y, iv1.z, iv1.w };
        int lm[K_] = { mv0.x, mv0.y, mv0.z, mv0.w, mv1.x, mv1.y, mv1.z, mv1.w };

        int lv[K_];
        int cnt = 0;
        #pragma unroll
        for (int k = 0; k < K_; k++) {
            int v = (lm[k] != 0) & (li[k] < L_) & (li[k] >= 0);
            li[k] = min(max(li[k], 0), L_ - 1);
            lv[k] = v;
            cnt  += v;
        }

        int pown  = (p < 4) ? ((const int*)&pv0)[p] : ((const int*)&pv1)[p - 4];
        int npred = (pv0.x != 0) + (pv0.y != 0) + (pv0.z != 0) + (pv0.w != 0)
                  + (pv1.x != 0) + (pv1.y != 0) + (pv1.z != 0) + (pv1.w != 0);

        float w = 0.0f;
        if (pown != 0 && cnt > 0 && npred > 0)
            w = 1.0f / ((float)cnt * (float)npred);

        if (w != 0.0f) {
            int pos = atomicAdd(&s_n[role], cnt);
            #pragma unroll
            for (int k = 0; k < K_; k++) {
                if (lv[k]) {
                    s_idx[role][pos] = li[k];
                    s_w[role][pos]   = w;
                    pos++;
                }
            }
        }
    }
    __syncthreads();

    // Phase 2: weighted row-sum over this CTA's H-half; MLP=4 batches.
    const float4* __restrict__ emb4 =
        reinterpret_cast<const float4*>(emb) + (size_t)s * L_ * H4_ + hhalf * HH4_ + tid;

    float4 a0 = make_float4(0.f, 0.f, 0.f, 0.f);
    float4 a1 = a0, a2 = a0;

    const int n0 = (s_n[0] + 3) & ~3;
    const int n1 = (s_n[1] + 3) & ~3;
    const int n2 = (s_n[2] + 3) & ~3;

    #define AXPY_LOOP(ACC, R, NR)                                              \
    for (int j = 0; j < (NR); j += 4) {                                        \
        int   i0 = s_idx[R][j+0], i1 = s_idx[R][j+1];                          \
        int   i2 = s_idx[R][j+2], i3 = s_idx[R][j+3];                          \
        float4 v0 = emb4[i0 * H4_];                                            \
        float4 v1 = emb4[i1 * H4_];                                            \
        float4 v2 = emb4[i2 * H4_];                                            \
        float4 v3 = emb4[i3 * H4_];                                            \
        float w0 = s_w[R][j+0], w1 = s_w[R][j+1];                              \
        float w2 = s_w[R][j+2], w3 = s_w[R][j+3];                              \
        ACC.x += w0*v0.x; ACC.y += w0*v0.y; ACC.z += w0*v0.z; ACC.w += w0*v0.w; \
        ACC.x += w1*v1.x; ACC.y += w1*v1.y; ACC.z += w1*v1.z; ACC.w += w1*v1.w; \
        ACC.x += w2*v2.x; ACC.y += w2*v2.y; ACC.z += w2*v2.z; ACC.w += w2*v2.w; \
        ACC.x += w3*v3.x; ACC.y += w3*v3.y; ACC.z += w3*v3.z; ACC.w += w3*v3.w; \
    }

    AXPY_LOOP(a0, 0, n0)
    AXPY_LOOP(a1, 1, n1)
    AXPY_LOOP(a2, 2, n2)
    #undef AXPY_LOOP

    // Output: (e_V, e_A0, e_A1) role-major, each (S, H) f32.
    float4* __restrict__ out4 =
        reinterpret_cast<float4*>(out) + (size_t)s * H4_ + hhalf * HH4_ + tid;
    out4[(size_t)0 * S_ * H4_] = a0;
    out4[(size_t)1 * S_ * H4_] = a1;
    out4[(size_t)2 * S_ * H4_] = a2;
}

extern "C" void kernel_launch(void* const* d_in, const int* in_sizes, int n_in,
                              void* d_out, int out_size)
{
    const float* emb   = (const float*)d_in[0];
    const int*   idxV  = (const int*)d_in[1];
    const int*   mV    = (const int*)d_in[2];
    const int*   idxA0 = (const int*)d_in[3];
    const int*   mA0   = (const int*)d_in[4];
    const int*   idxA1 = (const int*)d_in[5];
    const int*   mA1   = (const int*)d_in[6];
    const int*   pred  = (const int*)d_in[7];
    float* out = (float*)d_out;

    dim3 grid(S_, 2);
    srl_pool_kernel<<<grid, THREADS_>>>(emb, idxV, mV, idxA0, mA0, idxA1, mA1, pred, out);
}